// round 1
// baseline (speedup 1.0000x reference)
#include <cuda_runtime.h>
#include <cstdint>
#include <cstddef>

// ---------------- compile-time bounds (instance: B=16, Lmax=1984, N=24064, D=512) ----
#define LMAX     2048
#define SEGMAX   16
#define BMAX     64
#define NTOK_MAX 32768
#define DMAX     512

#define BM 64
#define BN 64
#define BK 16
#define PAD 4

// ---------------- device scratch (no allocations allowed) ----------------
__device__ float g_x[(size_t)NTOK_MAX * DMAX];                  // projected features x = hW^T+b
__device__ float g_scores[(size_t)SEGMAX * LMAX * LMAX];        // per-segment score/prob matrices
__device__ int   g_len[BMAX];
__device__ int   g_off[BMAX];

// ---------------- segment offsets (handles int32 or int64 lengths buffer) ----------
__global__ void offsets_kernel(const int* __restrict__ lens_raw, int count, int ntok) {
    if (threadIdx.x != 0 || blockIdx.x != 0) return;
    // int64 little-endian looks like [v0,0,v1,0,...] when viewed as int32
    bool is64 = (count >= 2) && (lens_raw[1] == 0) && (lens_raw[0] != 0);
    int acc = 0;
    for (int i = 0; i < BMAX; i++) {
        int L = 0;
        if (i < count && acc < ntok) L = lens_raw[is64 ? 2 * i : i];
        if (L < 0) L = 0;
        if (L > LMAX) L = LMAX;
        g_len[i] = L;
        g_off[i] = acc;
        acc += L;
    }
}

// ---------------- shared NT micro-kernel body: C = A * B^T (+bias) -----------------
// A: M x K (lda), B: N x K (ldb), C: M x N (ldc). 256 threads, 4x4 microtile.
__device__ __forceinline__ void gemm_nt_body(
    const float* __restrict__ A, const float* __restrict__ B,
    float* __restrict__ C, const float* __restrict__ bias,
    int M, int N, int K, int lda, int ldb, int ldc,
    int row0, int col0)
{
    __shared__ float As[BK][BM + PAD];
    __shared__ float Bs[BK][BN + PAD];
    const int tid = threadIdx.x;
    const int tx = tid & 15, ty = tid >> 4;
    float acc[4][4] = {};

    for (int k0 = 0; k0 < K; k0 += BK) {
        #pragma unroll
        for (int i = tid; i < BM * BK; i += 256) {
            int m = i >> 4, k = i & 15;
            int gr = row0 + m, gk = k0 + k;
            As[k][m] = (gr < M && gk < K) ? A[(size_t)gr * lda + gk] : 0.f;
        }
        #pragma unroll
        for (int i = tid; i < BN * BK; i += 256) {
            int n = i >> 4, k = i & 15;
            int gc = col0 + n, gk = k0 + k;
            Bs[k][n] = (gc < N && gk < K) ? B[(size_t)gc * ldb + gk] : 0.f;
        }
        __syncthreads();
        #pragma unroll
        for (int k = 0; k < BK; k++) {
            float a[4], bv[4];
            #pragma unroll
            for (int i = 0; i < 4; i++) a[i] = As[k][ty * 4 + i];
            #pragma unroll
            for (int j = 0; j < 4; j++) bv[j] = Bs[k][tx * 4 + j];
            #pragma unroll
            for (int i = 0; i < 4; i++)
                #pragma unroll
                for (int j = 0; j < 4; j++)
                    acc[i][j] += a[i] * bv[j];
        }
        __syncthreads();
    }

    #pragma unroll
    for (int i = 0; i < 4; i++) {
        int gr = row0 + ty * 4 + i;
        if (gr >= M) continue;
        #pragma unroll
        for (int j = 0; j < 4; j++) {
            int gc = col0 + tx * 4 + j;
            if (gc >= N) continue;
            float v = acc[i][j];
            if (bias) v += bias[gc];
            C[(size_t)gr * ldc + gc] = v;
        }
    }
}

// ---------------- kernel 1: x = h @ W^T + b ----------------
__global__ void linear_kernel(const float* __restrict__ h, const float* __restrict__ W,
                              const float* __restrict__ bias, int Ntok, int D)
{
    gemm_nt_body(h, W, g_x, bias, Ntok, D, D, D, D, D,
                 blockIdx.x * BM, blockIdx.y * BN);
}

// ---------------- kernel 2: per-segment S = Z Y^T ----------------
__global__ void scores_kernel(const float* __restrict__ h, int D)
{
    int b = blockIdx.z;
    int L = g_len[b];
    int row0 = blockIdx.y * BM;
    int col0 = blockIdx.x * BN;
    if (L == 0 || row0 >= L || col0 >= L) return;
    int off = g_off[b];
    const float* Z = h + (size_t)off * D;
    const float* Y = g_x + (size_t)off * D;
    float* S = g_scores + (size_t)b * LMAX * LMAX;
    gemm_nt_body(Z, Y, S, nullptr, L, L, D, D, D, LMAX, row0, col0);
}

// ---------------- kernel 3: row softmax over valid keys ----------------
__global__ void softmax_kernel()
{
    int b = blockIdx.y;
    int l = blockIdx.x;
    int L = g_len[b];
    if (l >= L) return;
    float* row = g_scores + (size_t)b * LMAX * LMAX + (size_t)l * LMAX;
    int tid = threadIdx.x;

    float v[LMAX / 256];
    float mx = -1e30f;
    #pragma unroll
    for (int i = 0; i < LMAX / 256; i++) {
        int m = tid + i * 256;
        v[i] = (m < L) ? row[m] : -1e30f;
        mx = fmaxf(mx, v[i]);
    }
    __shared__ float red[256];
    red[tid] = mx; __syncthreads();
    #pragma unroll
    for (int s = 128; s > 0; s >>= 1) {
        if (tid < s) red[tid] = fmaxf(red[tid], red[tid + s]);
        __syncthreads();
    }
    mx = red[0]; __syncthreads();

    float sum = 0.f;
    #pragma unroll
    for (int i = 0; i < LMAX / 256; i++) {
        int m = tid + i * 256;
        v[i] = (m < L) ? __expf(v[i] - mx) : 0.f;
        sum += v[i];
    }
    red[tid] = sum; __syncthreads();
    #pragma unroll
    for (int s = 128; s > 0; s >>= 1) {
        if (tid < s) red[tid] += red[tid + s];
        __syncthreads();
    }
    float inv = 1.f / red[0];

    #pragma unroll
    for (int i = 0; i < LMAX / 256; i++) {
        int m = tid + i * 256;
        if (m < L) row[m] = v[i] * inv;
    }
}

// ---------------- kernel 4: O = P Z, written to packed output ----------------
__global__ void out_kernel(const float* __restrict__ h, float* __restrict__ out, int D)
{
    int b = blockIdx.z;
    int L = g_len[b];
    if (L == 0) return;
    int row0 = blockIdx.y * BM;
    if (row0 >= L) return;
    int col0 = blockIdx.x * BN;
    int off = g_off[b];
    const float* P = g_scores + (size_t)b * LMAX * LMAX;
    const float* Z = h + (size_t)off * D;

    __shared__ float As[BK][BM + PAD];
    __shared__ float Bs[BK][BN + PAD];
    const int tid = threadIdx.x;
    const int tx = tid & 15, ty = tid >> 4;
    float acc[4][4] = {};

    for (int k0 = 0; k0 < L; k0 += BK) {
        #pragma unroll
        for (int i = tid; i < BM * BK; i += 256) {
            int m = i >> 4, k = i & 15;
            int gr = row0 + m, gk = k0 + k;
            As[k][m] = (gr < L && gk < L) ? P[(size_t)gr * LMAX + gk] : 0.f;
        }
        #pragma unroll
        for (int i = tid; i < BK * BN; i += 256) {
            int k = i >> 6, n = i & 63;   // coalesced over n (BN=64)
            int gk = k0 + k;
            Bs[k][n] = (gk < L) ? Z[(size_t)gk * D + col0 + n] : 0.f;
        }
        __syncthreads();
        #pragma unroll
        for (int k = 0; k < BK; k++) {
            float a[4], bv[4];
            #pragma unroll
            for (int i = 0; i < 4; i++) a[i] = As[k][ty * 4 + i];
            #pragma unroll
            for (int j = 0; j < 4; j++) bv[j] = Bs[k][tx * 4 + j];
            #pragma unroll
            for (int i = 0; i < 4; i++)
                #pragma unroll
                for (int j = 0; j < 4; j++)
                    acc[i][j] += a[i] * bv[j];
        }
        __syncthreads();
    }

    #pragma unroll
    for (int i = 0; i < 4; i++) {
        int gr = row0 + ty * 4 + i;
        if (gr >= L) continue;
        #pragma unroll
        for (int j = 0; j < 4; j++) {
            out[(size_t)(off + gr) * D + col0 + tx * 4 + j] = acc[i][j];
        }
    }
}

// ---------------- launch ----------------
extern "C" void kernel_launch(void* const* d_in, const int* in_sizes, int n_in,
                              void* d_out, int out_size)
{
    const float* h    = (const float*)d_in[0];
    const float* W    = (const float*)d_in[1];
    const float* bias = (const float*)d_in[2];
    const int*   lens = (const int*)d_in[3];

    int D    = in_sizes[2];            // bias length = feature dim (512)
    int Ntok = in_sizes[0] / D;        // packed token count (24064)
    int B    = in_sizes[3];            // segment count (16; may be 2x if int64 counted as words)
    if (B > BMAX) B = BMAX;

    offsets_kernel<<<1, 32>>>(lens, B, Ntok);

    dim3 blk(256);
    dim3 g1((Ntok + BM - 1) / BM, (D + BN - 1) / BN);
    linear_kernel<<<g1, blk>>>(h, W, bias, Ntok, D);

    dim3 g2(LMAX / BN, LMAX / BM, B);
    scores_kernel<<<g2, blk>>>(h, D);

    softmax_kernel<<<dim3(LMAX, B), 256>>>();

    dim3 g3((D + BN - 1) / BN, LMAX / BM, B);
    out_kernel<<<g3, blk>>>(h, (float*)d_out, D);
}